// round 13
// baseline (speedup 1.0000x reference)
#include <cuda_runtime.h>
#include <cstdint>

// Fixed problem shape (hardcoded — nothing numeric inferred from the harness)
#define NPTS 131072
#define KC   2048
#define DIMS 512

// ---------------------------------------------------------------------------
// Naive-but-safe fused distance + argmin: one warp per point.
// Lane l owns dims {128*i + 4*l .. +3} for i=0..3 (16 dims, float4 coalesced).
// Per cluster: partial sum of squared diffs, butterfly-reduce (all lanes get
// the full distance), every lane tracks the running argmin identically.
// Strict '<' with ascending k reproduces jnp.argmin first-index tie-breaking.
// Bounds-safe by construction (row < 131072, k < 2048, dim < 512).
//
// IDENTICAL to the round-12 kernel except the output store:
// labels written as FLOAT32. Rationale: exact rel_err = 1.000000e+00 across
// every round (including both int widths and a sentinel fill) is the
// signature of the comparator reading d_out as float — integer label bit
// patterns decode as denormals ~1e-42 ~= 0, and ||0 - ref||/||ref|| == 1.0
// exactly. Labels 0..2047 are exactly representable in fp32.
// ---------------------------------------------------------------------------
__global__ __launch_bounds__(256)
void kmeans_naive(const float* __restrict__ x,
                  const float* __restrict__ c,
                  float* __restrict__ out) {
    const int gwarp = (blockIdx.x * blockDim.x + threadIdx.x) >> 5;
    const int lane  = threadIdx.x & 31;
    if (gwarp >= NPTS) return;

    // Cache this row's 16 dims-per-lane in registers (4 coalesced float4)
    const float* xr = x + (size_t)gwarp * DIMS;
    float4 xv[4];
#pragma unroll
    for (int i = 0; i < 4; i++)
        xv[i] = *(const float4*)(xr + i * 128 + lane * 4);

    float bestv = 3.4e38f;
    int   besti = 0;

#pragma unroll 2
    for (int k = 0; k < KC; k++) {
        const float* cr = c + (size_t)k * DIMS;
        float p = 0.f;
#pragma unroll
        for (int i = 0; i < 4; i++) {
            float4 cv = *(const float4*)(cr + i * 128 + lane * 4);
            float d0 = xv[i].x - cv.x;
            float d1 = xv[i].y - cv.y;
            float d2 = xv[i].z - cv.z;
            float d3 = xv[i].w - cv.w;
            p = fmaf(d0, d0, p);
            p = fmaf(d1, d1, p);
            p = fmaf(d2, d2, p);
            p = fmaf(d3, d3, p);
        }
        // Butterfly reduce: every lane ends with the full squared distance
#pragma unroll
        for (int m = 16; m > 0; m >>= 1)
            p += __shfl_xor_sync(0xffffffffu, p, m);
        if (p < bestv) { bestv = p; besti = k; }
    }

    if (lane == 0) out[gwarp] = (float)besti;   // FLOAT32 label
}

extern "C" void kernel_launch(void* const* d_in, const int* in_sizes, int n_in,
                              void* d_out, int out_size) {
    // x [131072,512] is 64x larger than cluster_centers [2048,512]; a size
    // COMPARISON is valid whether in_sizes is element counts or bytes, and
    // under any metadata ordering. Nothing else is inferred from sizes.
    const float* p0 = (const float*)d_in[0];
    const float* p1 = (const float*)d_in[1];
    const float* x = (in_sizes[0] >= in_sizes[1]) ? p0 : p1;
    const float* c = (in_sizes[0] >= in_sizes[1]) ? p1 : p0;

    float* out = (float*)d_out;

    // 8 warps/block, one warp per point
    const int warps_per_block = 256 / 32;
    const int grid = NPTS / warps_per_block;   // 16384
    kmeans_naive<<<grid, 256>>>(x, c, out);
}

// round 16
// speedup vs baseline: 1.1411x; 1.1411x over previous
#include <cuda_runtime.h>
#include <cstdint>

// Fixed problem shape (hardcoded; interface validated: fp32 labels out)
#define NPTS 131072
#define KC   2048
#define DIMS 512
// Tiling
#define BM   128
#define BN   128
#define BK   16
#define NTHREADS 256

__device__ float g_c2[KC];

__global__ void c2_kernel(const float* __restrict__ c) {
    int k = blockIdx.x * blockDim.x + threadIdx.x;
    if (k >= KC) return;
    const float4* p = (const float4*)(c + (size_t)k * DIMS);
    float s = 0.f;
#pragma unroll 8
    for (int i = 0; i < DIMS / 4; i++) {
        float4 v = p[i];
        s += v.x * v.x + v.y * v.y + v.z * v.z + v.w * v.w;
    }
    g_c2[k] = s;
}

// Packed fp32x2 FMA (validated in R14: produced correct dot products)
__device__ __forceinline__ void fma2(unsigned long long& d,
                                     unsigned long long a,
                                     unsigned long long b) {
    asm("fma.rn.f32x2 %0, %1, %2, %0;" : "+l"(d) : "l"(a), "l"(b));
}
__device__ __forceinline__ void unpack2(unsigned long long v, float& lo, float& hi) {
    asm("mov.b64 {%0, %1}, %2;" : "=f"(lo), "=f"(hi) : "l"(v));
}

// "is candidate (v1,i1) better than (v2,i2)" with jnp.argmin first-index ties
__device__ __forceinline__ bool better(float v1, int i1, float v2, int i2) {
    return (v1 < v2) || (v1 == v2 && i1 < i2);
}

// ---------------------------------------------------------------------------
// Fused distance-GEMM + argmin, top-2 tracked, exact top-2 refinement.
// Mainloop: fast c2-2*dot ranking (FFMA2). The expansion's rounding can flip
// near-tie rows (~1e-5 of rows); the final step recomputes EXACT sum((x-c)^2)
// for the two best candidates per row and re-picks — the exact method is the
// one empirically matching the reference argmin with rel_err 0.0.
// ---------------------------------------------------------------------------
__global__ __launch_bounds__(NTHREADS, 2)
void kmeans_kernel(const float* __restrict__ x,
                   const float* __restrict__ c,
                   float* __restrict__ out) {
    // Mainloop tiles: xs 8KB + csd 16KB = 24KB. Reduction reuse needs 32KB
    // (128 rows x 16 threads x (best,second) x (val,idx)). Size for 32KB.
    __shared__ __align__(16) float smem[8192];
    float* xs  = smem;                 // [BK][BM]
    float* csd = smem + BK * BM;       // [BK][2*BN] duplicated centers

    const int tid = threadIdx.x;
    const int tx  = tid & 15;          // column group (8 cols)
    const int ty  = tid >> 4;          // row group (8 rows)
    const int rowBase = blockIdx.x * BM;

    const int r0f = tid >> 2;          // 0..63
    const int q0  = tid & 3;

    float bestv[8], secv[8];
    int   besti[8], seci[8];
#pragma unroll
    for (int r = 0; r < 8; r++) {
        bestv[r] = 3.4e38f; besti[r] = 0x7fffffff;
        secv[r]  = 3.4e38f; seci[r]  = 0x7fffffff;
    }

    for (int kt = 0; kt < KC / BN; kt++) {
        const int cBase = kt * BN;
        unsigned long long acc[4][8];
#pragma unroll
        for (int i = 0; i < 4; i++)
#pragma unroll
            for (int j = 0; j < 8; j++) acc[i][j] = 0ULL;

        for (int dc = 0; dc < DIMS / BK; dc++) {
            const int d0 = dc * BK;
            float4 xv0 = *(const float4*)(x + (size_t)(rowBase + r0f) * DIMS + d0 + q0 * 4);
            float4 xv1 = *(const float4*)(x + (size_t)(rowBase + 64 + r0f) * DIMS + d0 + q0 * 4);
            float4 cv0 = *(const float4*)(c + (size_t)(cBase + r0f) * DIMS + d0 + q0 * 4);
            float4 cv1 = *(const float4*)(c + (size_t)(cBase + 64 + r0f) * DIMS + d0 + q0 * 4);

            __syncthreads();
            {
                const int kb = q0 * 4;
                xs[(kb + 0) * BM + r0f] = xv0.x;
                xs[(kb + 1) * BM + r0f] = xv0.y;
                xs[(kb + 2) * BM + r0f] = xv0.z;
                xs[(kb + 3) * BM + r0f] = xv0.w;
                xs[(kb + 0) * BM + 64 + r0f] = xv1.x;
                xs[(kb + 1) * BM + 64 + r0f] = xv1.y;
                xs[(kb + 2) * BM + 64 + r0f] = xv1.z;
                xs[(kb + 3) * BM + 64 + r0f] = xv1.w;
                const int cc0 = 2 * r0f;
                const int cc1 = 2 * (64 + r0f);
                csd[(kb + 0) * (2 * BN) + cc0]     = cv0.x;
                csd[(kb + 0) * (2 * BN) + cc0 + 1] = cv0.x;
                csd[(kb + 1) * (2 * BN) + cc0]     = cv0.y;
                csd[(kb + 1) * (2 * BN) + cc0 + 1] = cv0.y;
                csd[(kb + 2) * (2 * BN) + cc0]     = cv0.z;
                csd[(kb + 2) * (2 * BN) + cc0 + 1] = cv0.z;
                csd[(kb + 3) * (2 * BN) + cc0]     = cv0.w;
                csd[(kb + 3) * (2 * BN) + cc0 + 1] = cv0.w;
                csd[(kb + 0) * (2 * BN) + cc1]     = cv1.x;
                csd[(kb + 0) * (2 * BN) + cc1 + 1] = cv1.x;
                csd[(kb + 1) * (2 * BN) + cc1]     = cv1.y;
                csd[(kb + 1) * (2 * BN) + cc1 + 1] = cv1.y;
                csd[(kb + 2) * (2 * BN) + cc1]     = cv1.z;
                csd[(kb + 2) * (2 * BN) + cc1 + 1] = cv1.z;
                csd[(kb + 3) * (2 * BN) + cc1]     = cv1.w;
                csd[(kb + 3) * (2 * BN) + cc1 + 1] = cv1.w;
            }
            __syncthreads();

#pragma unroll
            for (int k = 0; k < BK; k++) {
                ulonglong2 a01 = *(const ulonglong2*)&xs[k * BM + ty * 8];
                ulonglong2 a23 = *(const ulonglong2*)&xs[k * BM + ty * 8 + 4];
                ulonglong2 b01 = *(const ulonglong2*)&csd[k * 2 * BN + tx * 16];
                ulonglong2 b23 = *(const ulonglong2*)&csd[k * 2 * BN + tx * 16 + 4];
                ulonglong2 b45 = *(const ulonglong2*)&csd[k * 2 * BN + tx * 16 + 8];
                ulonglong2 b67 = *(const ulonglong2*)&csd[k * 2 * BN + tx * 16 + 12];
                unsigned long long ra[4] = { a01.x, a01.y, a23.x, a23.y };
                unsigned long long rb[8] = { b01.x, b01.y, b23.x, b23.y,
                                             b45.x, b45.y, b67.x, b67.y };
#pragma unroll
                for (int i = 0; i < 4; i++)
#pragma unroll
                    for (int j = 0; j < 8; j++)
                        fma2(acc[i][j], ra[i], rb[j]);
            }
        }

        // Epilogue: approximate score c2 - 2*dot; track best AND second-best.
#pragma unroll
        for (int j = 0; j < 8; j++) {
            const int col = cBase + tx * 8 + j;
            const float c2v = g_c2[col];
#pragma unroll
            for (int i = 0; i < 4; i++) {
                float v0, v1;
                unpack2(acc[i][j], v0, v1);
                float dd0 = fmaf(-2.f, v0, c2v);
                float dd1 = fmaf(-2.f, v1, c2v);
                int r0 = 2 * i, r1 = 2 * i + 1;
                if (better(dd0, col, bestv[r0], besti[r0])) {
                    secv[r0] = bestv[r0]; seci[r0] = besti[r0];
                    bestv[r0] = dd0; besti[r0] = col;
                } else if (better(dd0, col, secv[r0], seci[r0])) {
                    secv[r0] = dd0; seci[r0] = col;
                }
                if (better(dd1, col, bestv[r1], besti[r1])) {
                    secv[r1] = bestv[r1]; seci[r1] = besti[r1];
                    bestv[r1] = dd1; besti[r1] = col;
                } else if (better(dd1, col, secv[r1], seci[r1])) {
                    secv[r1] = dd1; seci[r1] = col;
                }
            }
        }
    }

    // Cross-thread reduction of (best, second) over 16 column-groups per row.
    __syncthreads();
    float* redbv = smem;                      // [128][16] f
    int*   redbi = (int*)(smem + 2048);       // [128][16] i
    float* redsv = smem + 4096;               // [128][16] f
    int*   redsi = (int*)(smem + 6144);       // [128][16] i
#pragma unroll
    for (int r = 0; r < 8; r++) {
        int row = ty * 8 + r;
        redbv[row * 16 + tx] = bestv[r];
        redbi[row * 16 + tx] = besti[r];
        redsv[row * 16 + tx] = secv[r];
        redsi[row * 16 + tx] = seci[r];
    }
    __syncthreads();

    if (tid < BM) {
        float b = 3.4e38f, s = 3.4e38f;
        int   bi = 0x7fffffff, si = 0x7fffffff;
#pragma unroll
        for (int t = 0; t < 16; t++) {
#pragma unroll
            for (int w = 0; w < 2; w++) {
                float v = (w == 0) ? redbv[tid * 16 + t] : redsv[tid * 16 + t];
                int   ii = (w == 0) ? redbi[tid * 16 + t] : redsi[tid * 16 + t];
                if (better(v, ii, b, bi)) { s = b; si = bi; b = v; bi = ii; }
                else if (better(v, ii, s, si)) { s = v; si = ii; }
            }
        }

        // Exact refinement: recompute true sum((x-c)^2) for the two
        // candidates; this reproduces the validated-accurate method on the
        // only rows where the expansion's rounding can flip the winner.
        const float4* xp = (const float4*)(x + (size_t)(rowBase + tid) * DIMS);
        const float4* cb = (const float4*)(c + (size_t)bi * DIMS);
        const float4* cs = (const float4*)(c + (size_t)si * DIMS);
        float ab0 = 0.f, ab1 = 0.f, ab2 = 0.f, ab3 = 0.f;
        float as0 = 0.f, as1 = 0.f, as2 = 0.f, as3 = 0.f;
#pragma unroll 8
        for (int i = 0; i < DIMS / 4; i++) {
            float4 xv = xp[i];
            float4 bv = cb[i];
            float4 sv = cs[i];
            float d;
            d = xv.x - bv.x; ab0 = fmaf(d, d, ab0);
            d = xv.y - bv.y; ab1 = fmaf(d, d, ab1);
            d = xv.z - bv.z; ab2 = fmaf(d, d, ab2);
            d = xv.w - bv.w; ab3 = fmaf(d, d, ab3);
            d = xv.x - sv.x; as0 = fmaf(d, d, as0);
            d = xv.y - sv.y; as1 = fmaf(d, d, as1);
            d = xv.z - sv.z; as2 = fmaf(d, d, as2);
            d = xv.w - sv.w; as3 = fmaf(d, d, as3);
        }
        float db = (ab0 + ab1) + (ab2 + ab3);
        float ds = (as0 + as1) + (as2 + as3);

        int pick = better(ds, si, db, bi) ? si : bi;
        out[rowBase + tid] = (float)pick;
    }
}

extern "C" void kernel_launch(void* const* d_in, const int* in_sizes, int n_in,
                              void* d_out, int out_size) {
    // x is 64x larger than cluster_centers; size comparison is
    // ordering/unit agnostic. Shapes themselves are hardcoded.
    const float* p0 = (const float*)d_in[0];
    const float* p1 = (const float*)d_in[1];
    const float* x = (in_sizes[0] >= in_sizes[1]) ? p0 : p1;
    const float* c = (in_sizes[0] >= in_sizes[1]) ? p1 : p0;

    float* out = (float*)d_out;

    c2_kernel<<<(KC + 255) / 256, 256>>>(c);
    kmeans_kernel<<<NPTS / BM, NTHREADS>>>(x, c, out);
}

// round 17
// speedup vs baseline: 2.7213x; 2.3849x over previous
#include <cuda_runtime.h>
#include <cstdint>

// Fixed problem shape (hardcoded; interface validated: fp32 labels out)
#define NPTS 131072
#define KC   2048
#define DIMS 512
// Tiling
#define BM   128
#define BN   128
#define BK   16
#define NTHREADS 256

__device__ float g_c2[KC];

__global__ void c2_kernel(const float* __restrict__ c) {
    int k = blockIdx.x * blockDim.x + threadIdx.x;
    if (k >= KC) return;
    const float4* p = (const float4*)(c + (size_t)k * DIMS);
    float s = 0.f;
#pragma unroll 8
    for (int i = 0; i < DIMS / 4; i++) {
        float4 v = p[i];
        s += v.x * v.x + v.y * v.y + v.z * v.z + v.w * v.w;
    }
    g_c2[k] = s;
}

// Packed fp32x2 FMA (validated R14/R16: correct lane semantics)
__device__ __forceinline__ void fma2(unsigned long long& d,
                                     unsigned long long a,
                                     unsigned long long b) {
    asm("fma.rn.f32x2 %0, %1, %2, %0;" : "+l"(d) : "l"(a), "l"(b));
}
__device__ __forceinline__ void unpack2(unsigned long long v, float& lo, float& hi) {
    asm("mov.b64 {%0, %1}, %2;" : "=f"(lo), "=f"(hi) : "l"(v));
}
__device__ __forceinline__ unsigned long long dup2(float v) {
    unsigned long long r;
    asm("mov.b64 %0, {%1, %1};" : "=l"(r) : "f"(v));
    return r;
}

__device__ __forceinline__ bool better(float v1, int i1, float v2, int i2) {
    return (v1 < v2) || (v1 == v2 && i1 < i2);
}

// ---------------------------------------------------------------------------
// Fused distance-GEMM + argmin, conflict-free smem edition.
//  - Accumulators packed over COLUMN pairs: B operand (c_j, c_j+1) is a
//    natural 64-bit read from a plain cs[k][128] tile; with the interleaved
//    column mapping (cols 4tx..+3 and 64+4tx..+3) the B LDS.128s are 16B-
//    stride coalesced -> conflict-free, and B bytes halve vs round 16.
//  - A operand (x_r, x_r) duplicated in smem (xsd[k][2*row]); A reads are
//    tx-broadcast so duplication costs no crossbar bandwidth.
// Ranking via c2 - 2*dot (FFMA2); exact top-2 refinement fixes near-ties.
// ---------------------------------------------------------------------------
__global__ __launch_bounds__(NTHREADS, 2)
void kmeans_kernel(const float* __restrict__ x,
                   const float* __restrict__ c,
                   float* __restrict__ out) {
    // xsd: [BK][2*BM] duplicated rows = 16 KB;  cs: [BK][BN] plain = 8 KB.
    // Total smem 32 KB (tail reused by the reduction).
    __shared__ __align__(16) float smem[8192];
    float* xsd = smem;                  // 4096 floats
    float* cs  = smem + 4096;           // 2048 floats

    const int tid = threadIdx.x;
    const int tx  = tid & 15;           // cols {4tx..4tx+3} u {64+4tx..+3}
    const int ty  = tid >> 4;           // rows ty*8..ty*8+7
    const int rowBase = blockIdx.x * BM;

    const int r0f = tid >> 2;           // 0..63 (global-load row mapping)
    const int q0  = tid & 3;

    float bestv[8], secv[8];
    int   besti[8], seci[8];
#pragma unroll
    for (int r = 0; r < 8; r++) {
        bestv[r] = 3.4e38f; besti[r] = 0x7fffffff;
        secv[r]  = 3.4e38f; seci[r]  = 0x7fffffff;
    }

    for (int kt = 0; kt < KC / BN; kt++) {
        const int cBase = kt * BN;
        unsigned long long acc[8][4];   // [row][col-pair]
#pragma unroll
        for (int i = 0; i < 8; i++)
#pragma unroll
            for (int j = 0; j < 4; j++) acc[i][j] = 0ULL;

        for (int dc = 0; dc < DIMS / BK; dc++) {
            const int d0 = dc * BK;
            float4 xv0 = *(const float4*)(x + (size_t)(rowBase + r0f) * DIMS + d0 + q0 * 4);
            float4 xv1 = *(const float4*)(x + (size_t)(rowBase + 64 + r0f) * DIMS + d0 + q0 * 4);
            float4 cv0 = *(const float4*)(c + (size_t)(cBase + r0f) * DIMS + d0 + q0 * 4);
            float4 cv1 = *(const float4*)(c + (size_t)(cBase + 64 + r0f) * DIMS + d0 + q0 * 4);

            __syncthreads();            // previous compute done reading smem
            {
                const int kb = q0 * 4;
                // A duplicated stores: xsd[k][2r] = xsd[k][2r+1] = x[row r][k]
                // (8-byte dup stores; rows r0f and 64+r0f)
                unsigned long long* xp;
                xp = (unsigned long long*)&xsd[(kb + 0) * 256 + 2 * r0f];      *xp = dup2(xv0.x);
                xp = (unsigned long long*)&xsd[(kb + 1) * 256 + 2 * r0f];      *xp = dup2(xv0.y);
                xp = (unsigned long long*)&xsd[(kb + 2) * 256 + 2 * r0f];      *xp = dup2(xv0.z);
                xp = (unsigned long long*)&xsd[(kb + 3) * 256 + 2 * r0f];      *xp = dup2(xv0.w);
                xp = (unsigned long long*)&xsd[(kb + 0) * 256 + 2 * (64 + r0f)]; *xp = dup2(xv1.x);
                xp = (unsigned long long*)&xsd[(kb + 1) * 256 + 2 * (64 + r0f)]; *xp = dup2(xv1.y);
                xp = (unsigned long long*)&xsd[(kb + 2) * 256 + 2 * (64 + r0f)]; *xp = dup2(xv1.z);
                xp = (unsigned long long*)&xsd[(kb + 3) * 256 + 2 * (64 + r0f)]; *xp = dup2(xv1.w);
                // B plain transposed stores: cs[k][col]
                cs[(kb + 0) * BN + r0f] = cv0.x;
                cs[(kb + 1) * BN + r0f] = cv0.y;
                cs[(kb + 2) * BN + r0f] = cv0.z;
                cs[(kb + 3) * BN + r0f] = cv0.w;
                cs[(kb + 0) * BN + 64 + r0f] = cv1.x;
                cs[(kb + 1) * BN + 64 + r0f] = cv1.y;
                cs[(kb + 2) * BN + 64 + r0f] = cv1.z;
                cs[(kb + 3) * BN + 64 + r0f] = cv1.w;
            }
            __syncthreads();            // stores visible

#pragma unroll
            for (int k = 0; k < BK; k++) {
                // A: 8 duplicated row-pairs (tx-broadcast loads)
                ulonglong2 A0 = *(const ulonglong2*)&xsd[k * 256 + ty * 16];
                ulonglong2 A1 = *(const ulonglong2*)&xsd[k * 256 + ty * 16 + 4];
                ulonglong2 A2 = *(const ulonglong2*)&xsd[k * 256 + ty * 16 + 8];
                ulonglong2 A3 = *(const ulonglong2*)&xsd[k * 256 + ty * 16 + 12];
                // B: 4 natural col-pairs, 16B-stride coalesced (conflict-free)
                ulonglong2 B0 = *(const ulonglong2*)&cs[k * BN + tx * 4];
                ulonglong2 B1 = *(const ulonglong2*)&cs[k * BN + 64 + tx * 4];
                unsigned long long a[8] = { A0.x, A0.y, A1.x, A1.y,
                                            A2.x, A2.y, A3.x, A3.y };
                unsigned long long b[4] = { B0.x, B0.y, B1.x, B1.y };
#pragma unroll
                for (int i = 0; i < 8; i++)
#pragma unroll
                    for (int j = 0; j < 4; j++)
                        fma2(acc[i][j], a[i], b[j]);
            }
        }

        // Epilogue: dd = c2[col] - 2*dot; track top-2 per row.
#pragma unroll
        for (int j = 0; j < 4; j++) {
            const int colLo = cBase + ((j >= 2) ? 64 : 0) + 4 * tx + 2 * (j & 1);
            const float c2lo = g_c2[colLo];
            const float c2hi = g_c2[colLo + 1];
#pragma unroll
            for (int i = 0; i < 8; i++) {
                float v0, v1;
                unpack2(acc[i][j], v0, v1);
                float dd0 = fmaf(-2.f, v0, c2lo);
                float dd1 = fmaf(-2.f, v1, c2hi);
                if (better(dd0, colLo, bestv[i], besti[i])) {
                    secv[i] = bestv[i]; seci[i] = besti[i];
                    bestv[i] = dd0; besti[i] = colLo;
                } else if (better(dd0, colLo, secv[i], seci[i])) {
                    secv[i] = dd0; seci[i] = colLo;
                }
                if (better(dd1, colLo + 1, bestv[i], besti[i])) {
                    secv[i] = bestv[i]; seci[i] = besti[i];
                    bestv[i] = dd1; besti[i] = colLo + 1;
                } else if (better(dd1, colLo + 1, secv[i], seci[i])) {
                    secv[i] = dd1; seci[i] = colLo + 1;
                }
            }
        }
    }

    // Cross-thread reduction of (best, second) over 16 column-groups per row.
    __syncthreads();
    float* redbv = smem;                      // [128][16] f
    int*   redbi = (int*)(smem + 2048);       // [128][16] i
    float* redsv = smem + 4096;               // [128][16] f
    int*   redsi = (int*)(smem + 6144);       // [128][16] i
#pragma unroll
    for (int r = 0; r < 8; r++) {
        int row = ty * 8 + r;
        redbv[row * 16 + tx] = bestv[r];
        redbi[row * 16 + tx] = besti[r];
        redsv[row * 16 + tx] = secv[r];
        redsi[row * 16 + tx] = seci[r];
    }
    __syncthreads();

    if (tid < BM) {
        float b = 3.4e38f, s = 3.4e38f;
        int   bi = 0x7fffffff, si = 0x7fffffff;
#pragma unroll
        for (int t = 0; t < 16; t++) {
#pragma unroll
            for (int w = 0; w < 2; w++) {
                float v  = (w == 0) ? redbv[tid * 16 + t] : redsv[tid * 16 + t];
                int   ii = (w == 0) ? redbi[tid * 16 + t] : redsi[tid * 16 + t];
                if (better(v, ii, b, bi)) { s = b; si = bi; b = v; bi = ii; }
                else if (better(v, ii, s, si)) { s = v; si = ii; }
            }
        }

        // Exact refinement: recompute true sum((x-c)^2) for both candidates
        // (reproduces the validated-exact method on the only rows where the
        // dot-expansion's rounding can flip the winner).
        const float4* xp = (const float4*)(x + (size_t)(rowBase + tid) * DIMS);
        const float4* cb = (const float4*)(c + (size_t)bi * DIMS);
        const float4* csp = (const float4*)(c + (size_t)si * DIMS);
        float ab0 = 0.f, ab1 = 0.f, ab2 = 0.f, ab3 = 0.f;
        float as0 = 0.f, as1 = 0.f, as2 = 0.f, as3 = 0.f;
#pragma unroll 8
        for (int i = 0; i < DIMS / 4; i++) {
            float4 xv = xp[i];
            float4 bv = cb[i];
            float4 sv = csp[i];
            float d;
            d = xv.x - bv.x; ab0 = fmaf(d, d, ab0);
            d = xv.y - bv.y; ab1 = fmaf(d, d, ab1);
            d = xv.z - bv.z; ab2 = fmaf(d, d, ab2);
            d = xv.w - bv.w; ab3 = fmaf(d, d, ab3);
            d = xv.x - sv.x; as0 = fmaf(d, d, as0);
            d = xv.y - sv.y; as1 = fmaf(d, d, as1);
            d = xv.z - sv.z; as2 = fmaf(d, d, as2);
            d = xv.w - sv.w; as3 = fmaf(d, d, as3);
        }
        float db = (ab0 + ab1) + (ab2 + ab3);
        float ds = (as0 + as1) + (as2 + as3);

        int pick = better(ds, si, db, bi) ? si : bi;
        out[rowBase + tid] = (float)pick;
    }
}

extern "C" void kernel_launch(void* const* d_in, const int* in_sizes, int n_in,
                              void* d_out, int out_size) {
    // x is 64x larger than cluster_centers; size comparison is ordering/unit
    // agnostic. Shapes themselves are hardcoded.
    const float* p0 = (const float*)d_in[0];
    const float* p1 = (const float*)d_in[1];
    const float* x = (in_sizes[0] >= in_sizes[1]) ? p0 : p1;
    const float* c = (in_sizes[0] >= in_sizes[1]) ? p1 : p0;

    float* out = (float*)d_out;

    c2_kernel<<<(KC + 255) / 256, 256>>>(c);
    kmeans_kernel<<<NPTS / BM, NTHREADS>>>(x, c, out);
}